// round 1
// baseline (speedup 1.0000x reference)
#include <cuda_runtime.h>
#include <cuda_bf16.h>
#include <cstdint>

#define N_NODES   100000
#define N_EDGES   1600000
#define N_WEIGHTS 256
#define D         16
#define TILE      256

// ---------------- scratch (device globals; re-initialized every launch) ----------------
__device__ int g_bin_count[N_WEIGHTS];
__device__ int g_bin_start[N_WEIGHTS + 1];
__device__ int g_bin_fill[N_WEIGHTS];
__device__ int g_su[N_EDGES];
__device__ int g_sv[N_EDGES];

// ---------------- kernels ----------------

__global__ void init_k() {
    int t = blockIdx.x * blockDim.x + threadIdx.x;
    if (t < N_WEIGHTS) g_bin_count[t] = 0;
}

__global__ void hist_k(const int* __restrict__ widx, int E) {
    __shared__ int h[N_WEIGHTS];
    int t = threadIdx.x;
    if (t < N_WEIGHTS) h[t] = 0;
    __syncthreads();
    int stride = gridDim.x * blockDim.x;
    for (int e = blockIdx.x * blockDim.x + t; e < E; e += stride)
        atomicAdd(&h[widx[e]], 1);
    __syncthreads();
    if (t < N_WEIGHTS && h[t]) atomicAdd(&g_bin_count[t], h[t]);
}

__global__ void scan_k() {
    __shared__ int s[N_WEIGHTS];
    int t = threadIdx.x;
    int v = g_bin_count[t];
    s[t] = v;
    __syncthreads();
    // Hillis-Steele inclusive scan
    for (int off = 1; off < N_WEIGHTS; off <<= 1) {
        int add = (t >= off) ? s[t - off] : 0;
        __syncthreads();
        s[t] += add;
        __syncthreads();
    }
    g_bin_start[t + 1] = s[t];
    if (t == 0) g_bin_start[0] = 0;
    g_bin_fill[t] = s[t] - v;   // exclusive prefix = fill base
}

__global__ void scatter_k(const int* __restrict__ u, const int* __restrict__ v,
                          const int* __restrict__ widx, int E) {
    // E % 32 == 0 and warp-aligned bases -> all lanes of a warp run the same
    // trip count, so full-mask warp intrinsics are safe.
    int stride = gridDim.x * blockDim.x;
    int lane = threadIdx.x & 31;
    for (int e = blockIdx.x * blockDim.x + threadIdx.x; e < E; e += stride) {
        int w  = widx[e];
        int uu = u[e];
        int vv = v[e];
        unsigned m = __match_any_sync(0xffffffffu, w);
        int leader = __ffs(m) - 1;
        int rank   = __popc(m & ((1u << lane) - 1));
        int base   = 0;
        if (lane == leader) base = atomicAdd(&g_bin_fill[w], __popc(m));
        base = __shfl_sync(0xffffffffu, base, leader);
        int pos = base + rank;
        g_su[pos] = uu;
        g_sv[pos] = vv;
    }
}

__device__ __forceinline__ void red_add_v4(float* p, float a, float b, float c, float d) {
    asm volatile("red.global.add.v4.f32 [%0], {%1, %2, %3, %4};"
                 :: "l"(p), "f"(a), "f"(b), "f"(c), "f"(d) : "memory");
}

// Main edge kernel: one widx bin per blockIdx.x; W held in registers
// (4 output rows per thread, 4 threads per edge).
__global__ void __launch_bounds__(256, 2)
edge_mm_k(const float* __restrict__ x, const float* __restrict__ W,
          float* __restrict__ out) {
    const int w  = blockIdx.x;
    const int bs = g_bin_start[w];
    const int be = g_bin_start[w + 1];

    const int tid   = threadIdx.x;
    const int obase = (tid & 3) * 4;   // output rows [obase, obase+4)
    const int el0   = tid >> 2;        // edge slot 0..63

    // Load my 4 W rows into registers (16 floats per row)
    const float4* Wp = (const float4*)(W + (size_t)w * (D * D));
    float4 wr[4][4];
#pragma unroll
    for (int r = 0; r < 4; r++)
#pragma unroll
        for (int q = 0; q < 4; q++)
            wr[r][q] = Wp[(obase + r) * 4 + q];

    __shared__ int    s_u[TILE];
    __shared__ int    s_v[TILE];
    __shared__ float4 xs[TILE * 5];    // padded (stride 5 float4s) -> conflict-free

    const float4* x4 = (const float4*)x;

    for (int base = bs + blockIdx.y * TILE; base < be; base += gridDim.y * TILE) {
        const int n = min(TILE, be - base);

        __syncthreads();   // protect smem from previous iteration's readers
        if (tid < n) {
            s_u[tid] = g_su[base + tid];
            s_v[tid] = g_sv[base + tid];
        }
        __syncthreads();

        // stage x rows of this tile (4 x float4 per edge)
        for (int j = tid; j < n * 4; j += 256) {
            int e = j >> 2, q = j & 3;
            xs[e * 5 + q] = x4[(size_t)s_u[e] * 4 + q];
        }
        __syncthreads();

#pragma unroll
        for (int it = 0; it < TILE / 64; ++it) {
            int e = el0 + it * 64;
            if (e < n) {
                float a[4] = {0.f, 0.f, 0.f, 0.f};
#pragma unroll
                for (int q = 0; q < 4; q++) {
                    float4 xq = xs[e * 5 + q];
#pragma unroll
                    for (int r = 0; r < 4; r++) {
                        a[r] += wr[r][q].x * xq.x + wr[r][q].y * xq.y
                              + wr[r][q].z * xq.z + wr[r][q].w * xq.w;
                    }
                }
                float* dst = out + (size_t)s_v[e] * D + obase;
                red_add_v4(dst, a[0], a[1], a[2], a[3]);
            }
        }
    }
}

__global__ void relu_k(float* __restrict__ out, int n4) {
    int stride = gridDim.x * blockDim.x;
    float4* o4 = (float4*)out;
    for (int i = blockIdx.x * blockDim.x + threadIdx.x; i < n4; i += stride) {
        float4 v = o4[i];
        v.x = fmaxf(v.x, 0.f);
        v.y = fmaxf(v.y, 0.f);
        v.z = fmaxf(v.z, 0.f);
        v.w = fmaxf(v.w, 0.f);
        o4[i] = v;
    }
}

// ---------------- launcher ----------------
extern "C" void kernel_launch(void* const* d_in, const int* in_sizes, int n_in,
                              void* d_out, int out_size) {
    const float* x    = (const float*)d_in[0];
    const float* W    = (const float*)d_in[1];
    const int*   u    = (const int*)d_in[2];
    const int*   v    = (const int*)d_in[3];
    const int*   widx = (const int*)d_in[4];
    float* out = (float*)d_out;

    const int E = in_sizes[2];   // 1,600,000

    cudaMemsetAsync(d_out, 0, (size_t)out_size * sizeof(float), 0);

    init_k<<<1, 256>>>();
    hist_k<<<512, 256>>>(widx, E);
    scan_k<<<1, 256>>>();
    scatter_k<<<1024, 256>>>(u, v, widx, E);
    edge_mm_k<<<dim3(N_WEIGHTS, 12), 256>>>(x, W, out);
    relu_k<<<784, 256>>>(out, out_size / 4);
}

// round 2
// speedup vs baseline: 4.1885x; 4.1885x over previous
#include <cuda_runtime.h>
#include <cuda_bf16.h>
#include <cstdint>

#define N_NODES   100000
#define N_EDGES   1600000
#define N_WEIGHTS 256
#define D         16
#define TILE      256
#define SC_ITER   8
#define SC_CHUNK  (256 * SC_ITER)   // 2048 edges per scatter block

// ---------------- scratch (device globals; re-initialized every launch) ----------------
__device__ int  g_bin_count[N_WEIGHTS];
__device__ int  g_bin_start[N_WEIGHTS + 1];
__device__ int  g_bin_fill[N_WEIGHTS];
__device__ int2 g_suv[N_EDGES];

// ---------------- kernels ----------------

__global__ void init_k() {
    int t = blockIdx.x * blockDim.x + threadIdx.x;
    if (t < N_WEIGHTS) g_bin_count[t] = 0;
}

__global__ void hist_k(const int* __restrict__ widx, int E) {
    __shared__ int h[N_WEIGHTS];
    int t = threadIdx.x;
    if (t < N_WEIGHTS) h[t] = 0;
    __syncthreads();
    int stride = gridDim.x * blockDim.x;
    for (int e = blockIdx.x * blockDim.x + t; e < E; e += stride)
        atomicAdd(&h[widx[e]], 1);
    __syncthreads();
    if (t < N_WEIGHTS && h[t]) atomicAdd(&g_bin_count[t], h[t]);
}

__global__ void scan_k() {
    __shared__ int s[N_WEIGHTS];
    int t = threadIdx.x;
    int v = g_bin_count[t];
    s[t] = v;
    __syncthreads();
    // Hillis-Steele inclusive scan
    for (int off = 1; off < N_WEIGHTS; off <<= 1) {
        int add = (t >= off) ? s[t - off] : 0;
        __syncthreads();
        s[t] += add;
        __syncthreads();
    }
    g_bin_start[t + 1] = s[t];
    if (t == 0) g_bin_start[0] = 0;
    g_bin_fill[t] = s[t] - v;   // exclusive prefix = fill base
}

// Block-aggregated counting-sort scatter:
//   local smem ranks -> one global atomicAdd per (block,bin) -> scattered writes.
__global__ void __launch_bounds__(256)
scatter_k(const int* __restrict__ u, const int* __restrict__ v,
          const int* __restrict__ widx, int E) {
    __shared__ int cnt[N_WEIGHTS];
    __shared__ int base[N_WEIGHTS];

    const int tid = threadIdx.x;
    const int blk0 = blockIdx.x * SC_CHUNK;
    if (blk0 >= E) return;

    if (tid < N_WEIGHTS) cnt[tid] = 0;
    __syncthreads();

    int eu[SC_ITER], ev[SC_ITER], ew[SC_ITER], er[SC_ITER];
#pragma unroll
    for (int i = 0; i < SC_ITER; i++) {
        int e = blk0 + tid + i * 256;
        if (e < E) {
            ew[i] = widx[e];
            eu[i] = u[e];
            ev[i] = v[e];
            er[i] = atomicAdd(&cnt[ew[i]], 1);   // smem atomic, spread addrs
        }
    }
    __syncthreads();

    if (tid < N_WEIGHTS) {
        int c = cnt[tid];
        base[tid] = c ? atomicAdd(&g_bin_fill[tid], c) : 0;
    }
    __syncthreads();

#pragma unroll
    for (int i = 0; i < SC_ITER; i++) {
        int e = blk0 + tid + i * 256;
        if (e < E) {
            int pos = base[ew[i]] + er[i];
            g_suv[pos] = make_int2(eu[i], ev[i]);
        }
    }
}

__device__ __forceinline__ void red_add_v4(float* p, float a, float b, float c, float d) {
    asm volatile("red.global.add.v4.f32 [%0], {%1, %2, %3, %4};"
                 :: "l"(p), "f"(a), "f"(b), "f"(c), "f"(d) : "memory");
}

// Main edge kernel: one widx bin per blockIdx.x; W held in registers
// (4 output rows per thread, 4 threads per edge).
__global__ void __launch_bounds__(256, 2)
edge_mm_k(const float* __restrict__ x, const float* __restrict__ W,
          float* __restrict__ out) {
    const int w  = blockIdx.x;
    const int bs = g_bin_start[w];
    const int be = g_bin_start[w + 1];

    const int tid   = threadIdx.x;
    const int obase = (tid & 3) * 4;   // output rows [obase, obase+4)
    const int el0   = tid >> 2;        // edge slot 0..63

    // Load my 4 W rows into registers (16 floats per row)
    const float4* Wp = (const float4*)(W + (size_t)w * (D * D));
    float4 wr[4][4];
#pragma unroll
    for (int r = 0; r < 4; r++)
#pragma unroll
        for (int q = 0; q < 4; q++)
            wr[r][q] = Wp[(obase + r) * 4 + q];

    __shared__ int    s_v[TILE];
    __shared__ float4 xs[TILE * 5];    // padded (stride 5 float4s) -> conflict-free

    const float4* x4 = (const float4*)x;

    for (int base = bs + blockIdx.y * TILE; base < be; base += gridDim.y * TILE) {
        const int n = min(TILE, be - base);

        __syncthreads();   // protect smem from previous iteration's readers
        if (tid < n) {
            int2 uv = g_suv[base + tid];
            s_v[tid] = uv.y;
            // stage this edge's x row directly (4 float4 loads by owner thread)
            const float4* xr = x4 + (size_t)uv.x * 4;
            xs[tid * 5 + 0] = xr[0];
            xs[tid * 5 + 1] = xr[1];
            xs[tid * 5 + 2] = xr[2];
            xs[tid * 5 + 3] = xr[3];
        }
        __syncthreads();

#pragma unroll
        for (int it = 0; it < TILE / 64; ++it) {
            int e = el0 + it * 64;
            if (e < n) {
                float a[4] = {0.f, 0.f, 0.f, 0.f};
#pragma unroll
                for (int q = 0; q < 4; q++) {
                    float4 xq = xs[e * 5 + q];
#pragma unroll
                    for (int r = 0; r < 4; r++) {
                        a[r] += wr[r][q].x * xq.x + wr[r][q].y * xq.y
                              + wr[r][q].z * xq.z + wr[r][q].w * xq.w;
                    }
                }
                float* dst = out + (size_t)s_v[e] * D + obase;
                red_add_v4(dst, a[0], a[1], a[2], a[3]);
            }
        }
    }
}

__global__ void relu_k(float* __restrict__ out, int n4) {
    int stride = gridDim.x * blockDim.x;
    float4* o4 = (float4*)out;
    for (int i = blockIdx.x * blockDim.x + threadIdx.x; i < n4; i += stride) {
        float4 v = o4[i];
        v.x = fmaxf(v.x, 0.f);
        v.y = fmaxf(v.y, 0.f);
        v.z = fmaxf(v.z, 0.f);
        v.w = fmaxf(v.w, 0.f);
        o4[i] = v;
    }
}

// ---------------- launcher ----------------
extern "C" void kernel_launch(void* const* d_in, const int* in_sizes, int n_in,
                              void* d_out, int out_size) {
    const float* x    = (const float*)d_in[0];
    const float* W    = (const float*)d_in[1];
    const int*   u    = (const int*)d_in[2];
    const int*   v    = (const int*)d_in[3];
    const int*   widx = (const int*)d_in[4];
    float* out = (float*)d_out;

    const int E = in_sizes[2];   // 1,600,000

    cudaMemsetAsync(d_out, 0, (size_t)out_size * sizeof(float), 0);

    init_k<<<1, 256>>>();
    hist_k<<<512, 256>>>(widx, E);
    scan_k<<<1, 256>>>();
    scatter_k<<<(E + SC_CHUNK - 1) / SC_CHUNK, 256>>>(u, v, widx, E);
    edge_mm_k<<<dim3(N_WEIGHTS, 12), 256>>>(x, W, out);
    relu_k<<<784, 256>>>(out, out_size / 4);
}

// round 3
// speedup vs baseline: 4.3543x; 1.0396x over previous
#include <cuda_runtime.h>
#include <cuda_bf16.h>
#include <cstdint>

#define N_NODES   100000
#define N_EDGES   1600000
#define N_WEIGHTS 256
#define D         16
#define TILE      256
#define SC_ITER   16
#define SC_CHUNK  (256 * SC_ITER)   // 4096 edges per scatter block

// ---------------- scratch ----------------
__device__ int  g_bin_count[N_WEIGHTS];
__device__ int  g_bin_start[N_WEIGHTS + 1];
__device__ int  g_bin_fill[N_WEIGHTS];
__device__ int2 g_suv[N_EDGES];

// ---------------- helpers ----------------
__device__ __forceinline__ unsigned long long pack2(float lo, float hi) {
    unsigned long long r;
    asm("mov.b64 %0, {%1, %2};" : "=l"(r) : "f"(lo), "f"(hi));
    return r;
}
__device__ __forceinline__ void fma2(unsigned long long& d,
                                     unsigned long long a, unsigned long long b) {
    asm("fma.rn.f32x2 %0, %1, %2, %0;" : "+l"(d) : "l"(a), "l"(b));
}
__device__ __forceinline__ void unpack2(unsigned long long v, float& lo, float& hi) {
    asm("mov.b64 {%0, %1}, %2;" : "=f"(lo), "=f"(hi) : "l"(v));
}
__device__ __forceinline__ void red_add_v4(float* p, float a, float b, float c, float d) {
    asm volatile("red.global.add.v4.f32 [%0], {%1, %2, %3, %4};"
                 :: "l"(p), "f"(a), "f"(b), "f"(c), "f"(d) : "memory");
}

// ---------------- kernels ----------------

__global__ void init_k() {
    int t = blockIdx.x * blockDim.x + threadIdx.x;
    if (t < N_WEIGHTS) g_bin_count[t] = 0;
}

__global__ void hist_k(const int* __restrict__ widx, int E) {
    __shared__ int h[N_WEIGHTS];
    int t = threadIdx.x;
    if (t < N_WEIGHTS) h[t] = 0;
    __syncthreads();
    const int4* w4 = (const int4*)widx;
    int n4 = E >> 2;
    int stride = gridDim.x * blockDim.x;
    for (int i = blockIdx.x * blockDim.x + t; i < n4; i += stride) {
        int4 w = w4[i];
        atomicAdd(&h[w.x], 1);
        atomicAdd(&h[w.y], 1);
        atomicAdd(&h[w.z], 1);
        atomicAdd(&h[w.w], 1);
    }
    __syncthreads();
    if (t < N_WEIGHTS && h[t]) atomicAdd(&g_bin_count[t], h[t]);
}

__global__ void scan_k() {
    __shared__ int s[N_WEIGHTS];
    int t = threadIdx.x;
    int v = g_bin_count[t];
    s[t] = v;
    __syncthreads();
    for (int off = 1; off < N_WEIGHTS; off <<= 1) {
        int add = (t >= off) ? s[t - off] : 0;
        __syncthreads();
        s[t] += add;
        __syncthreads();
    }
    g_bin_start[t + 1] = s[t];
    if (t == 0) g_bin_start[0] = 0;
    g_bin_fill[t] = s[t] - v;
}

// Counting-sort scatter with smem staging for coalesced global writes.
__global__ void __launch_bounds__(256)
scatter_k(const int* __restrict__ u, const int* __restrict__ v,
          const int* __restrict__ widx, int E) {
    __shared__ int  cnt[N_WEIGHTS];
    __shared__ int  lstart[N_WEIGHTS];   // exclusive local scan
    __shared__ int  gbase[N_WEIGHTS];
    __shared__ int2 sval[SC_CHUNK];
    __shared__ unsigned char sbin[SC_CHUNK];

    const int tid  = threadIdx.x;
    const int blk0 = blockIdx.x * SC_CHUNK;
    if (blk0 >= E) return;
    const int n = min(SC_CHUNK, E - blk0);

    if (tid < N_WEIGHTS) cnt[tid] = 0;
    __syncthreads();

    int eu[SC_ITER], ev[SC_ITER], ew[SC_ITER], er[SC_ITER];
#pragma unroll
    for (int i = 0; i < SC_ITER; i++) {
        int e = blk0 + tid + i * 256;
        if (e < E) {
            ew[i] = widx[e];
            eu[i] = u[e];
            ev[i] = v[e];
            er[i] = atomicAdd(&cnt[ew[i]], 1);
        }
    }
    __syncthreads();

    // block-level exclusive scan of cnt + per-bin global base
    {
        int c = cnt[tid];
        int s = c;
        __shared__ int tmp[N_WEIGHTS];
        tmp[tid] = s;
        __syncthreads();
        for (int off = 1; off < N_WEIGHTS; off <<= 1) {
            int add = (tid >= off) ? tmp[tid - off] : 0;
            __syncthreads();
            tmp[tid] += add;
            __syncthreads();
        }
        lstart[tid] = tmp[tid] - c;
        gbase[tid] = c ? atomicAdd(&g_bin_fill[tid], c) : 0;
    }
    __syncthreads();

    // place into local sorted order
#pragma unroll
    for (int i = 0; i < SC_ITER; i++) {
        int e = blk0 + tid + i * 256;
        if (e < E) {
            int slot = lstart[ew[i]] + er[i];
            sval[slot] = make_int2(eu[i], ev[i]);
            sbin[slot] = (unsigned char)ew[i];
        }
    }
    __syncthreads();

    // coalesced-ish global writes: bin runs are contiguous
    for (int s = tid; s < n; s += 256) {
        int b = sbin[s];
        g_suv[gbase[b] + (s - lstart[b])] = sval[s];
    }
}

// Main edge kernel: one widx bin per blockIdx.x; W in registers as f32x2 pairs.
__global__ void __launch_bounds__(256)
edge_mm_k(const float* __restrict__ x, const float* __restrict__ W,
          float* __restrict__ out) {
    const int w  = blockIdx.x;
    const int bs = g_bin_start[w];
    const int be = g_bin_start[w + 1];

    const int tid   = threadIdx.x;
    const int obase = (tid & 3) * 4;   // output rows [obase, obase+4)
    const int el0   = tid >> 2;        // edge slot 0..63

    // Pack W rows: pair0 = rows(obase,obase+1), pair1 = rows(obase+2,obase+3)
    const float* Wb = W + (size_t)w * (D * D);
    unsigned long long wp0[D], wp1[D];
#pragma unroll
    for (int k = 0; k < D; k++) {
        wp0[k] = pack2(Wb[(obase + 0) * D + k], Wb[(obase + 1) * D + k]);
        wp1[k] = pack2(Wb[(obase + 2) * D + k], Wb[(obase + 3) * D + k]);
    }

    __shared__ int2   s_uv[TILE];
    __shared__ float4 xs[TILE * 5];    // stride-5 float4 padding

    const float4* x4 = (const float4*)x;

    for (int base = bs + blockIdx.y * TILE; base < be; base += gridDim.y * TILE) {
        const int n = min(TILE, be - base);

        __syncthreads();
        if (tid < n) s_uv[tid] = g_suv[base + tid];
        __syncthreads();

        // cooperative x gather: 4 consecutive lanes cover one edge's 64B row
        for (int j = tid; j < n * 4; j += 256) {
            int e = j >> 2, q = j & 3;
            xs[e * 5 + q] = x4[(size_t)s_uv[e].x * 4 + q];
        }
        __syncthreads();

#pragma unroll
        for (int it = 0; it < TILE / 64; ++it) {
            int e = el0 + it * 64;
            if (e < n) {
                unsigned long long acc0 = 0ull, acc1 = 0ull;
#pragma unroll
                for (int q = 0; q < 4; q++) {
                    float4 xq = xs[e * 5 + q];
                    unsigned long long b0 = pack2(xq.x, xq.x);
                    unsigned long long b1 = pack2(xq.y, xq.y);
                    unsigned long long b2 = pack2(xq.z, xq.z);
                    unsigned long long b3 = pack2(xq.w, xq.w);
                    fma2(acc0, wp0[q * 4 + 0], b0);  fma2(acc1, wp1[q * 4 + 0], b0);
                    fma2(acc0, wp0[q * 4 + 1], b1);  fma2(acc1, wp1[q * 4 + 1], b1);
                    fma2(acc0, wp0[q * 4 + 2], b2);  fma2(acc1, wp1[q * 4 + 2], b2);
                    fma2(acc0, wp0[q * 4 + 3], b3);  fma2(acc1, wp1[q * 4 + 3], b3);
                }
                float a0, a1, a2, a3;
                unpack2(acc0, a0, a1);
                unpack2(acc1, a2, a3);
                float* dst = out + (size_t)s_uv[e].y * D + obase;
                red_add_v4(dst, a0, a1, a2, a3);
            }
        }
    }
}

__global__ void relu_k(float* __restrict__ out, int n4) {
    int stride = gridDim.x * blockDim.x;
    float4* o4 = (float4*)out;
    for (int i = blockIdx.x * blockDim.x + threadIdx.x; i < n4; i += stride) {
        float4 v = o4[i];
        v.x = fmaxf(v.x, 0.f);
        v.y = fmaxf(v.y, 0.f);
        v.z = fmaxf(v.z, 0.f);
        v.w = fmaxf(v.w, 0.f);
        o4[i] = v;
    }
}

// ---------------- launcher ----------------
extern "C" void kernel_launch(void* const* d_in, const int* in_sizes, int n_in,
                              void* d_out, int out_size) {
    const float* x    = (const float*)d_in[0];
    const float* W    = (const float*)d_in[1];
    const int*   u    = (const int*)d_in[2];
    const int*   v    = (const int*)d_in[3];
    const int*   widx = (const int*)d_in[4];
    float* out = (float*)d_out;

    const int E = in_sizes[2];

    cudaMemsetAsync(d_out, 0, (size_t)out_size * sizeof(float), 0);

    init_k<<<1, 256>>>();
    hist_k<<<512, 256>>>(widx, E);
    scan_k<<<1, 256>>>();
    scatter_k<<<(E + SC_CHUNK - 1) / SC_CHUNK, 256>>>(u, v, widx, E);
    edge_mm_k<<<dim3(N_WEIGHTS, 12), 256>>>(x, W, out);
    relu_k<<<784, 256>>>(out, out_size / 4);
}

// round 4
// speedup vs baseline: 5.1096x; 1.1734x over previous
#include <cuda_runtime.h>
#include <cuda_bf16.h>
#include <cstdint>

#define N_NODES   100000
#define N_EDGES   1600000
#define N_WEIGHTS 256
#define D         16
#define SC_ITER   16
#define SC_CHUNK  (256 * SC_ITER)   // 4096 edges per scatter block
#define MM_GRID_Y 3                 // blocks per bin in edge_mm

// ---------------- scratch ----------------
__device__ int  g_bin_count[N_WEIGHTS];
__device__ int  g_bin_start[N_WEIGHTS + 1];
__device__ int  g_bin_fill[N_WEIGHTS];
__device__ int2 g_suv[N_EDGES];

// ---------------- helpers ----------------
__device__ __forceinline__ unsigned long long pack2(float lo, float hi) {
    unsigned long long r;
    asm("mov.b64 %0, {%1, %2};" : "=l"(r) : "f"(lo), "f"(hi));
    return r;
}
__device__ __forceinline__ void fma2(unsigned long long& d,
                                     unsigned long long a, unsigned long long b) {
    asm("fma.rn.f32x2 %0, %1, %2, %0;" : "+l"(d) : "l"(a), "l"(b));
}
__device__ __forceinline__ void unpack2(unsigned long long v, float& lo, float& hi) {
    asm("mov.b64 {%0, %1}, %2;" : "=f"(lo), "=f"(hi) : "l"(v));
}
__device__ __forceinline__ void red_add_v4(float* p, float a, float b, float c, float d) {
    asm volatile("red.global.add.v4.f32 [%0], {%1, %2, %3, %4};"
                 :: "l"(p), "f"(a), "f"(b), "f"(c), "f"(d) : "memory");
}

// ---------------- kernels ----------------

__global__ void init_k() {
    int t = blockIdx.x * blockDim.x + threadIdx.x;
    if (t < N_WEIGHTS) g_bin_count[t] = 0;
}

__global__ void hist_k(const int* __restrict__ widx, int E) {
    __shared__ int h[N_WEIGHTS];
    int t = threadIdx.x;
    if (t < N_WEIGHTS) h[t] = 0;
    __syncthreads();
    const int4* w4 = (const int4*)widx;
    int n4 = E >> 2;
    int stride = gridDim.x * blockDim.x;
    for (int i = blockIdx.x * blockDim.x + t; i < n4; i += stride) {
        int4 w = w4[i];
        atomicAdd(&h[w.x], 1);
        atomicAdd(&h[w.y], 1);
        atomicAdd(&h[w.z], 1);
        atomicAdd(&h[w.w], 1);
    }
    __syncthreads();
    if (t < N_WEIGHTS && h[t]) atomicAdd(&g_bin_count[t], h[t]);
}

__global__ void scan_k() {
    __shared__ int s[N_WEIGHTS];
    int t = threadIdx.x;
    int v = g_bin_count[t];
    s[t] = v;
    __syncthreads();
    for (int off = 1; off < N_WEIGHTS; off <<= 1) {
        int add = (t >= off) ? s[t - off] : 0;
        __syncthreads();
        s[t] += add;
        __syncthreads();
    }
    g_bin_start[t + 1] = s[t];
    if (t == 0) g_bin_start[0] = 0;
    g_bin_fill[t] = s[t] - v;
}

// Two-pass block-aggregated counting-sort scatter (smem/reg light).
__global__ void __launch_bounds__(256)
scatter_k(const int* __restrict__ u, const int* __restrict__ v,
          const int* __restrict__ widx, int E) {
    __shared__ int cnt[N_WEIGHTS];
    __shared__ int base[N_WEIGHTS];

    const int tid  = threadIdx.x;
    const int blk0 = blockIdx.x * SC_CHUNK;
    if (blk0 >= E) return;

    if (tid < N_WEIGHTS) cnt[tid] = 0;
    __syncthreads();

    int ew[SC_ITER];
#pragma unroll
    for (int i = 0; i < SC_ITER; i++) {
        int e = blk0 + tid + i * 256;
        if (e < E) {
            ew[i] = widx[e];
            atomicAdd(&cnt[ew[i]], 1);
        }
    }
    __syncthreads();

    if (tid < N_WEIGHTS) {
        int c = cnt[tid];
        base[tid] = c ? atomicAdd(&g_bin_fill[tid], c) : 0;
    }
    __syncthreads();

#pragma unroll
    for (int i = 0; i < SC_ITER; i++) {
        int e = blk0 + tid + i * 256;
        if (e < E) {
            int pos = atomicAdd(&base[ew[i]], 1);
            g_suv[pos] = make_int2(u[e], v[e]);
        }
    }
}

// Warp-autonomous edge kernel: one widx bin per blockIdx.x, W in registers,
// each warp pipelines two independent 8-edge groups with only __syncwarp.
__global__ void __launch_bounds__(256)
edge_mm_k(const float* __restrict__ x, const float* __restrict__ W,
          float* __restrict__ out) {
    const int w  = blockIdx.x;
    const int bs = g_bin_start[w];
    const int be = g_bin_start[w + 1];

    const int tid   = threadIdx.x;
    const int lane  = tid & 31;
    const int wid   = tid >> 5;                 // warp in block (0..7)
    const int qrt   = lane & 3;                 // quarter index (x-load & out-rows)
    const int el    = lane >> 2;                // edge slot in group (0..7)
    const int obase = qrt * 4;

    // W rows [obase, obase+4) packed as f32x2 pairs
    const float* Wb = W + (size_t)w * (D * D);
    unsigned long long wp0[D], wp1[D];
#pragma unroll
    for (int k = 0; k < D; k++) {
        wp0[k] = pack2(Wb[(obase + 0) * D + k], Wb[(obase + 1) * D + k]);
        wp1[k] = pack2(Wb[(obase + 2) * D + k], Wb[(obase + 3) * D + k]);
    }

    // warp-private staging: 16 edges x (4 quarters, stride 5 float4) = 1280B/warp
    __shared__ float4 xs[8][16 * 5];

    const float4* x4 = (const float4*)x;
    const int gw = blockIdx.y * 8 + wid;        // global warp index within bin
    const int nw = gridDim.y * 8;

    for (int e0 = bs + gw * 16; e0 < be; e0 += nw * 16) {
        const int eA = e0 + el;
        const int eB = e0 + 8 + el;
        const bool pA = eA < be;
        const bool pB = eB < be;

        int2 uvA = pA ? g_suv[eA] : make_int2(0, 0);
        int2 uvB = pB ? g_suv[eB] : make_int2(0, 0);

        float4 xqA = x4[(size_t)uvA.x * 4 + qrt];
        float4 xqB = x4[(size_t)uvB.x * 4 + qrt];

        xs[wid][el * 5 + qrt]        = xqA;
        xs[wid][(8 + el) * 5 + qrt]  = xqB;
        __syncwarp();

        unsigned long long a0A = 0ull, a1A = 0ull, a0B = 0ull, a1B = 0ull;
#pragma unroll
        for (int q = 0; q < 4; q++) {
            float4 xA = xs[wid][el * 5 + q];
            float4 xB = xs[wid][(8 + el) * 5 + q];
            unsigned long long bA0 = pack2(xA.x, xA.x), bB0 = pack2(xB.x, xB.x);
            unsigned long long bA1 = pack2(xA.y, xA.y), bB1 = pack2(xB.y, xB.y);
            unsigned long long bA2 = pack2(xA.z, xA.z), bB2 = pack2(xB.z, xB.z);
            unsigned long long bA3 = pack2(xA.w, xA.w), bB3 = pack2(xB.w, xB.w);
            fma2(a0A, wp0[q * 4 + 0], bA0);  fma2(a1A, wp1[q * 4 + 0], bA0);
            fma2(a0B, wp0[q * 4 + 0], bB0);  fma2(a1B, wp1[q * 4 + 0], bB0);
            fma2(a0A, wp0[q * 4 + 1], bA1);  fma2(a1A, wp1[q * 4 + 1], bA1);
            fma2(a0B, wp0[q * 4 + 1], bB1);  fma2(a1B, wp1[q * 4 + 1], bB1);
            fma2(a0A, wp0[q * 4 + 2], bA2);  fma2(a1A, wp1[q * 4 + 2], bA2);
            fma2(a0B, wp0[q * 4 + 2], bB2);  fma2(a1B, wp1[q * 4 + 2], bB2);
            fma2(a0A, wp0[q * 4 + 3], bA3);  fma2(a1A, wp1[q * 4 + 3], bA3);
            fma2(a0B, wp0[q * 4 + 3], bB3);  fma2(a1B, wp1[q * 4 + 3], bB3);
        }

        if (pA) {
            float r0, r1, r2, r3;
            unpack2(a0A, r0, r1);
            unpack2(a1A, r2, r3);
            red_add_v4(out + (size_t)uvA.y * D + obase, r0, r1, r2, r3);
        }
        if (pB) {
            float r0, r1, r2, r3;
            unpack2(a0B, r0, r1);
            unpack2(a1B, r2, r3);
            red_add_v4(out + (size_t)uvB.y * D + obase, r0, r1, r2, r3);
        }
        __syncwarp();   // protect xs before next iteration overwrites
    }
}

__global__ void relu_k(float* __restrict__ out, int n4) {
    int stride = gridDim.x * blockDim.x;
    float4* o4 = (float4*)out;
    for (int i = blockIdx.x * blockDim.x + threadIdx.x; i < n4; i += stride) {
        float4 v = o4[i];
        v.x = fmaxf(v.x, 0.f);
        v.y = fmaxf(v.y, 0.f);
        v.z = fmaxf(v.z, 0.f);
        v.w = fmaxf(v.w, 0.f);
        o4[i] = v;
    }
}

// ---------------- launcher ----------------
extern "C" void kernel_launch(void* const* d_in, const int* in_sizes, int n_in,
                              void* d_out, int out_size) {
    const float* x    = (const float*)d_in[0];
    const float* W    = (const float*)d_in[1];
    const int*   u    = (const int*)d_in[2];
    const int*   v    = (const int*)d_in[3];
    const int*   widx = (const int*)d_in[4];
    float* out = (float*)d_out;

    const int E = in_sizes[2];

    cudaMemsetAsync(d_out, 0, (size_t)out_size * sizeof(float), 0);

    init_k<<<1, 256>>>();
    hist_k<<<512, 256>>>(widx, E);
    scan_k<<<1, 256>>>();
    scatter_k<<<(E + SC_CHUNK - 1) / SC_CHUNK, 256>>>(u, v, widx, E);
    edge_mm_k<<<dim3(N_WEIGHTS, MM_GRID_Y), 256>>>(x, W, out);
    relu_k<<<784, 256>>>(out, out_size / 4);
}

// round 5
// speedup vs baseline: 5.6912x; 1.1138x over previous
#include <cuda_runtime.h>
#include <cuda_bf16.h>
#include <cstdint>

#define N_NODES   100000
#define N_EDGES   1600000
#define N_WEIGHTS 256
#define D         16
#define SC_ITER   8
#define SC_CHUNK  (256 * SC_ITER)   // 2048 edges per scatter block
#define MM_GRID_Y 6                 // blocks per bin in edge_mm

// ---------------- scratch ----------------
__device__ int  g_bin_count[N_WEIGHTS];
__device__ int  g_bin_start[N_WEIGHTS + 1];
__device__ int  g_bin_fill[N_WEIGHTS];
__device__ int2 g_suv[N_EDGES];

// ---------------- helpers ----------------
__device__ __forceinline__ unsigned long long pack2(float lo, float hi) {
    unsigned long long r;
    asm("mov.b64 %0, {%1, %2};" : "=l"(r) : "f"(lo), "f"(hi));
    return r;
}
__device__ __forceinline__ void fma2(unsigned long long& d,
                                     unsigned long long a, unsigned long long b) {
    asm("fma.rn.f32x2 %0, %1, %2, %0;" : "+l"(d) : "l"(a), "l"(b));
}
__device__ __forceinline__ void unpack2(unsigned long long v, float& lo, float& hi) {
    asm("mov.b64 {%0, %1}, %2;" : "=f"(lo), "=f"(hi) : "l"(v));
}
__device__ __forceinline__ void red_add_v4(float* p, float a, float b, float c, float d) {
    asm volatile("red.global.add.v4.f32 [%0], {%1, %2, %3, %4};"
                 :: "l"(p), "f"(a), "f"(b), "f"(c), "f"(d) : "memory");
}

// ---------------- kernels ----------------

__global__ void init_k() {
    int t = blockIdx.x * blockDim.x + threadIdx.x;
    if (t < N_WEIGHTS) g_bin_count[t] = 0;
}

__global__ void hist_k(const int* __restrict__ widx, int E) {
    __shared__ int h[N_WEIGHTS];
    int t = threadIdx.x;
    if (t < N_WEIGHTS) h[t] = 0;
    __syncthreads();
    const int4* w4 = (const int4*)widx;
    int n4 = E >> 2;
    int stride = gridDim.x * blockDim.x;
    for (int i = blockIdx.x * blockDim.x + t; i < n4; i += stride) {
        int4 w = w4[i];
        atomicAdd(&h[w.x], 1);
        atomicAdd(&h[w.y], 1);
        atomicAdd(&h[w.z], 1);
        atomicAdd(&h[w.w], 1);
    }
    __syncthreads();
    if (t < N_WEIGHTS && h[t]) atomicAdd(&g_bin_count[t], h[t]);
}

__global__ void scan_k() {
    __shared__ int s[N_WEIGHTS];
    int t = threadIdx.x;
    int v = g_bin_count[t];
    s[t] = v;
    __syncthreads();
    for (int off = 1; off < N_WEIGHTS; off <<= 1) {
        int add = (t >= off) ? s[t - off] : 0;
        __syncthreads();
        s[t] += add;
        __syncthreads();
    }
    g_bin_start[t + 1] = s[t];
    if (t == 0) g_bin_start[0] = 0;
    g_bin_fill[t] = s[t] - v;
}

// Counting-sort scatter: local ranks in regs, smem staging, coalesced writes.
__global__ void __launch_bounds__(256)
scatter_k(const int* __restrict__ u, const int* __restrict__ v,
          const int* __restrict__ widx, int E) {
    __shared__ int  cnt[N_WEIGHTS];
    __shared__ int  tmp[N_WEIGHTS];
    __shared__ int  lstart[N_WEIGHTS];
    __shared__ int  gbase[N_WEIGHTS];
    __shared__ int2 sval[SC_CHUNK];
    __shared__ unsigned char sbin[SC_CHUNK];

    const int tid  = threadIdx.x;
    const int blk0 = blockIdx.x * SC_CHUNK;
    if (blk0 >= E) return;
    const int n = min(SC_CHUNK, E - blk0);

    if (tid < N_WEIGHTS) cnt[tid] = 0;
    __syncthreads();

    int eu[SC_ITER], ev[SC_ITER], ew[SC_ITER], er[SC_ITER];
#pragma unroll
    for (int i = 0; i < SC_ITER; i++) {
        int e = blk0 + tid + i * 256;
        if (e < E) {
            ew[i] = widx[e];
            eu[i] = u[e];
            ev[i] = v[e];
            er[i] = atomicAdd(&cnt[ew[i]], 1);
        }
    }
    __syncthreads();

    {
        int c = cnt[tid];
        tmp[tid] = c;
        __syncthreads();
        for (int off = 1; off < N_WEIGHTS; off <<= 1) {
            int add = (tid >= off) ? tmp[tid - off] : 0;
            __syncthreads();
            tmp[tid] += add;
            __syncthreads();
        }
        lstart[tid] = tmp[tid] - c;
        gbase[tid]  = c ? atomicAdd(&g_bin_fill[tid], c) : 0;
    }
    __syncthreads();

#pragma unroll
    for (int i = 0; i < SC_ITER; i++) {
        int e = blk0 + tid + i * 256;
        if (e < E) {
            int slot = lstart[ew[i]] + er[i];
            sval[slot] = make_int2(eu[i], ev[i]);
            sbin[slot] = (unsigned char)ew[i];
        }
    }
    __syncthreads();

    // coalesced global writes: bin runs are contiguous
    for (int s = tid; s < n; s += 256) {
        int b = sbin[s];
        g_suv[gbase[b] + (s - lstart[b])] = sval[s];
    }
}

// Warp-autonomous edge kernel with uv software pipelining.
__global__ void __launch_bounds__(256)
edge_mm_k(const float* __restrict__ x, const float* __restrict__ W,
          float* __restrict__ out) {
    const int w  = blockIdx.x;
    const int bs = g_bin_start[w];
    const int be = g_bin_start[w + 1];

    const int tid   = threadIdx.x;
    const int lane  = tid & 31;
    const int wid   = tid >> 5;
    const int qrt   = lane & 3;
    const int el    = lane >> 2;
    const int obase = qrt * 4;

    const float* Wb = W + (size_t)w * (D * D);
    unsigned long long wp0[D], wp1[D];
#pragma unroll
    for (int k = 0; k < D; k++) {
        wp0[k] = pack2(Wb[(obase + 0) * D + k], Wb[(obase + 1) * D + k]);
        wp1[k] = pack2(Wb[(obase + 2) * D + k], Wb[(obase + 3) * D + k]);
    }

    __shared__ float4 xs[8][16 * 5];

    const float4* x4 = (const float4*)x;
    const int gw   = blockIdx.y * 8 + wid;
    const int step = gridDim.y * 8 * 16;

    int e0 = bs + gw * 16;
    if (e0 >= be) return;

    // prologue: load first iteration's uv
    int2 uvA = (e0 + el      < be) ? g_suv[e0 + el]      : make_int2(0, 0);
    int2 uvB = (e0 + 8 + el  < be) ? g_suv[e0 + 8 + el]  : make_int2(0, 0);

    for (; e0 < be; e0 += step) {
        const bool pA = (e0 + el     < be);
        const bool pB = (e0 + 8 + el < be);

        // x gather for current iteration (uv already resident)
        float4 xqA = x4[(size_t)uvA.x * 4 + qrt];
        float4 xqB = x4[(size_t)uvB.x * 4 + qrt];

        // prefetch next iteration's uv
        const int e1 = e0 + step;
        int2 nA = (e1 + el     < be) ? g_suv[e1 + el]     : make_int2(0, 0);
        int2 nB = (e1 + 8 + el < be) ? g_suv[e1 + 8 + el] : make_int2(0, 0);

        xs[wid][el * 5 + qrt]       = xqA;
        xs[wid][(8 + el) * 5 + qrt] = xqB;
        __syncwarp();

        unsigned long long a0A = 0ull, a1A = 0ull, a0B = 0ull, a1B = 0ull;
#pragma unroll
        for (int q = 0; q < 4; q++) {
            float4 xA = xs[wid][el * 5 + q];
            float4 xB = xs[wid][(8 + el) * 5 + q];
            unsigned long long bA0 = pack2(xA.x, xA.x), bB0 = pack2(xB.x, xB.x);
            unsigned long long bA1 = pack2(xA.y, xA.y), bB1 = pack2(xB.y, xB.y);
            unsigned long long bA2 = pack2(xA.z, xA.z), bB2 = pack2(xB.z, xB.z);
            unsigned long long bA3 = pack2(xA.w, xA.w), bB3 = pack2(xB.w, xB.w);
            fma2(a0A, wp0[q * 4 + 0], bA0);  fma2(a1A, wp1[q * 4 + 0], bA0);
            fma2(a0B, wp0[q * 4 + 0], bB0);  fma2(a1B, wp1[q * 4 + 0], bB0);
            fma2(a0A, wp0[q * 4 + 1], bA1);  fma2(a1A, wp1[q * 4 + 1], bA1);
            fma2(a0B, wp0[q * 4 + 1], bB1);  fma2(a1B, wp1[q * 4 + 1], bB1);
            fma2(a0A, wp0[q * 4 + 2], bA2);  fma2(a1A, wp1[q * 4 + 2], bA2);
            fma2(a0B, wp0[q * 4 + 2], bB2);  fma2(a1B, wp1[q * 4 + 2], bB2);
            fma2(a0A, wp0[q * 4 + 3], bA3);  fma2(a1A, wp1[q * 4 + 3], bA3);
            fma2(a0B, wp0[q * 4 + 3], bB3);  fma2(a1B, wp1[q * 4 + 3], bB3);
        }

        if (pA) {
            float r0, r1, r2, r3;
            unpack2(a0A, r0, r1);
            unpack2(a1A, r2, r3);
            red_add_v4(out + (size_t)uvA.y * D + obase, r0, r1, r2, r3);
        }
        if (pB) {
            float r0, r1, r2, r3;
            unpack2(a0B, r0, r1);
            unpack2(a1B, r2, r3);
            red_add_v4(out + (size_t)uvB.y * D + obase, r0, r1, r2, r3);
        }
        __syncwarp();

        uvA = nA;
        uvB = nB;
    }
}

__global__ void relu_k(float* __restrict__ out, int n4) {
    int stride = gridDim.x * blockDim.x;
    float4* o4 = (float4*)out;
    for (int i = blockIdx.x * blockDim.x + threadIdx.x; i < n4; i += stride) {
        float4 v = o4[i];
        v.x = fmaxf(v.x, 0.f);
        v.y = fmaxf(v.y, 0.f);
        v.z = fmaxf(v.z, 0.f);
        v.w = fmaxf(v.w, 0.f);
        o4[i] = v;
    }
}

// ---------------- launcher ----------------
extern "C" void kernel_launch(void* const* d_in, const int* in_sizes, int n_in,
                              void* d_out, int out_size) {
    const float* x    = (const float*)d_in[0];
    const float* W    = (const float*)d_in[1];
    const int*   u    = (const int*)d_in[2];
    const int*   v    = (const int*)d_in[3];
    const int*   widx = (const int*)d_in[4];
    float* out = (float*)d_out;

    const int E = in_sizes[2];

    cudaMemsetAsync(d_out, 0, (size_t)out_size * sizeof(float), 0);

    init_k<<<1, 256>>>();
    hist_k<<<512, 256>>>(widx, E);
    scan_k<<<1, 256>>>();
    scatter_k<<<(E + SC_CHUNK - 1) / SC_CHUNK, 256>>>(u, v, widx, E);
    edge_mm_k<<<dim3(N_WEIGHTS, MM_GRID_Y), 256>>>(x, W, out);
    relu_k<<<784, 256>>>(out, out_size / 4);
}

// round 6
// speedup vs baseline: 5.8295x; 1.0243x over previous
#include <cuda_runtime.h>
#include <cuda_bf16.h>
#include <cstdint>

#define N_NODES   100000
#define N_EDGES   1600000
#define N_WEIGHTS 256
#define D         16
#define SC_ITER   8
#define SC_CHUNK  (256 * SC_ITER)   // 2048 edges per scatter block
#define MM_GRID_Y 10                // blocks per bin in edge_mm
#define BIN_CAP   8192              // fixed slots per bin (≥ max bin count ~6600)

// ---------------- scratch ----------------
__device__ int  g_bin_fill[N_WEIGHTS];
__device__ int2 g_suv[N_WEIGHTS * BIN_CAP];

// ---------------- helpers ----------------
__device__ __forceinline__ unsigned long long pack2(float lo, float hi) {
    unsigned long long r;
    asm("mov.b64 %0, {%1, %2};" : "=l"(r) : "f"(lo), "f"(hi));
    return r;
}
__device__ __forceinline__ void fma2(unsigned long long& d,
                                     unsigned long long a, unsigned long long b) {
    asm("fma.rn.f32x2 %0, %1, %2, %0;" : "+l"(d) : "l"(a), "l"(b));
}
__device__ __forceinline__ void unpack2(unsigned long long v, float& lo, float& hi) {
    asm("mov.b64 {%0, %1}, %2;" : "=f"(lo), "=f"(hi) : "l"(v));
}
__device__ __forceinline__ void red_add_v4(float* p, float a, float b, float c, float d) {
    asm volatile("red.global.add.v4.f32 [%0], {%1, %2, %3, %4};"
                 :: "l"(p), "f"(a), "f"(b), "f"(c), "f"(d) : "memory");
}

// ---------------- kernels ----------------

__global__ void fill_init_k() {
    int t = threadIdx.x;
    g_bin_fill[t] = t * BIN_CAP;
}

// One-pass counting-sort scatter into bump-allocated bin regions.
// Local ranks via smem atomics, shuffle-based block scan, staged coalesced writes.
__global__ void __launch_bounds__(256)
scatter_k(const int* __restrict__ u, const int* __restrict__ v,
          const int* __restrict__ widx, int E) {
    __shared__ int  cnt[N_WEIGHTS];
    __shared__ int  lstart[N_WEIGHTS];
    __shared__ int  gbase[N_WEIGHTS];
    __shared__ int  wsum[8];
    __shared__ int2 sval[SC_CHUNK];
    __shared__ unsigned char sbin[SC_CHUNK];

    const int tid  = threadIdx.x;
    const int lane = tid & 31;
    const int wrp  = tid >> 5;
    const int blk0 = blockIdx.x * SC_CHUNK;
    if (blk0 >= E) return;
    const int n = min(SC_CHUNK, E - blk0);

    cnt[tid] = 0;
    __syncthreads();

    int eu[SC_ITER], ev[SC_ITER], ew[SC_ITER], er[SC_ITER];
#pragma unroll
    for (int i = 0; i < SC_ITER; i++) {
        int e = blk0 + tid + i * 256;
        if (e < E) {
            ew[i] = widx[e];
            eu[i] = u[e];
            ev[i] = v[e];
            er[i] = atomicAdd(&cnt[ew[i]], 1);
        }
    }
    __syncthreads();

    // shuffle-based exclusive block scan of cnt[256]
    {
        const int c = cnt[tid];
        int s = c;
#pragma unroll
        for (int off = 1; off < 32; off <<= 1) {
            int t = __shfl_up_sync(0xffffffffu, s, off);
            if (lane >= off) s += t;
        }
        if (lane == 31) wsum[wrp] = s;
        __syncthreads();
        if (wrp == 0 && lane < 8) {
            int t = wsum[lane];
#pragma unroll
            for (int off = 1; off < 8; off <<= 1) {
                int q = __shfl_up_sync(0xffu, t, off);
                if (lane >= off) t += q;
            }
            wsum[lane] = t;
        }
        __syncthreads();
        int incl = s + (wrp ? wsum[wrp - 1] : 0);
        lstart[tid] = incl - c;
        gbase[tid]  = c ? atomicAdd(&g_bin_fill[tid], c) : 0;
    }
    __syncthreads();

    // place into locally sorted staging
#pragma unroll
    for (int i = 0; i < SC_ITER; i++) {
        int e = blk0 + tid + i * 256;
        if (e < E) {
            int slot = lstart[ew[i]] + er[i];
            sval[slot] = make_int2(eu[i], ev[i]);
            sbin[slot] = (unsigned char)ew[i];
        }
    }
    __syncthreads();

    // coalesced global writes (bin runs contiguous)
    for (int s = tid; s < n; s += 256) {
        int b = sbin[s];
        g_suv[gbase[b] + (s - lstart[b])] = sval[s];
    }
}

// Warp-autonomous edge kernel with uv software pipelining.
__global__ void __launch_bounds__(256)
edge_mm_k(const float* __restrict__ x, const float* __restrict__ W,
          float* __restrict__ out) {
    const int w  = blockIdx.x;
    const int bs = w * BIN_CAP;
    const int be = g_bin_fill[w];      // post-scatter: bs + bin_count

    const int tid   = threadIdx.x;
    const int lane  = tid & 31;
    const int wid   = tid >> 5;
    const int qrt   = lane & 3;
    const int el    = lane >> 2;
    const int obase = qrt * 4;

    const float* Wb = W + (size_t)w * (D * D);
    unsigned long long wp0[D], wp1[D];
#pragma unroll
    for (int k = 0; k < D; k++) {
        wp0[k] = pack2(Wb[(obase + 0) * D + k], Wb[(obase + 1) * D + k]);
        wp1[k] = pack2(Wb[(obase + 2) * D + k], Wb[(obase + 3) * D + k]);
    }

    __shared__ float4 xs[8][16 * 5];

    const float4* x4 = (const float4*)x;
    const int gw   = blockIdx.y * 8 + wid;
    const int step = gridDim.y * 8 * 16;

    int e0 = bs + gw * 16;
    if (e0 >= be) return;

    int2 uvA = (e0 + el     < be) ? g_suv[e0 + el]     : make_int2(0, 0);
    int2 uvB = (e0 + 8 + el < be) ? g_suv[e0 + 8 + el] : make_int2(0, 0);

    for (; e0 < be; e0 += step) {
        const bool pA = (e0 + el     < be);
        const bool pB = (e0 + 8 + el < be);

        float4 xqA = x4[(size_t)uvA.x * 4 + qrt];
        float4 xqB = x4[(size_t)uvB.x * 4 + qrt];

        const int e1 = e0 + step;
        int2 nA = (e1 + el     < be) ? g_suv[e1 + el]     : make_int2(0, 0);
        int2 nB = (e1 + 8 + el < be) ? g_suv[e1 + 8 + el] : make_int2(0, 0);

        xs[wid][el * 5 + qrt]       = xqA;
        xs[wid][(8 + el) * 5 + qrt] = xqB;
        __syncwarp();

        unsigned long long a0A = 0ull, a1A = 0ull, a0B = 0ull, a1B = 0ull;
#pragma unroll
        for (int q = 0; q < 4; q++) {
            float4 xA = xs[wid][el * 5 + q];
            float4 xB = xs[wid][(8 + el) * 5 + q];
            unsigned long long bA0 = pack2(xA.x, xA.x), bB0 = pack2(xB.x, xB.x);
            unsigned long long bA1 = pack2(xA.y, xA.y), bB1 = pack2(xB.y, xB.y);
            unsigned long long bA2 = pack2(xA.z, xA.z), bB2 = pack2(xB.z, xB.z);
            unsigned long long bA3 = pack2(xA.w, xA.w), bB3 = pack2(xB.w, xB.w);
            fma2(a0A, wp0[q * 4 + 0], bA0);  fma2(a1A, wp1[q * 4 + 0], bA0);
            fma2(a0B, wp0[q * 4 + 0], bB0);  fma2(a1B, wp1[q * 4 + 0], bB0);
            fma2(a0A, wp0[q * 4 + 1], bA1);  fma2(a1A, wp1[q * 4 + 1], bA1);
            fma2(a0B, wp0[q * 4 + 1], bB1);  fma2(a1B, wp1[q * 4 + 1], bB1);
            fma2(a0A, wp0[q * 4 + 2], bA2);  fma2(a1A, wp1[q * 4 + 2], bA2);
            fma2(a0B, wp0[q * 4 + 2], bB2);  fma2(a1B, wp1[q * 4 + 2], bB2);
            fma2(a0A, wp0[q * 4 + 3], bA3);  fma2(a1A, wp1[q * 4 + 3], bA3);
            fma2(a0B, wp0[q * 4 + 3], bB3);  fma2(a1B, wp1[q * 4 + 3], bB3);
        }

        if (pA) {
            float r0, r1, r2, r3;
            unpack2(a0A, r0, r1);
            unpack2(a1A, r2, r3);
            red_add_v4(out + (size_t)uvA.y * D + obase, r0, r1, r2, r3);
        }
        if (pB) {
            float r0, r1, r2, r3;
            unpack2(a0B, r0, r1);
            unpack2(a1B, r2, r3);
            red_add_v4(out + (size_t)uvB.y * D + obase, r0, r1, r2, r3);
        }
        __syncwarp();

        uvA = nA;
        uvB = nB;
    }
}

__global__ void relu_k(float* __restrict__ out, int n4) {
    int stride = gridDim.x * blockDim.x;
    float4* o4 = (float4*)out;
    for (int i = blockIdx.x * blockDim.x + threadIdx.x; i < n4; i += stride) {
        float4 v = o4[i];
        v.x = fmaxf(v.x, 0.f);
        v.y = fmaxf(v.y, 0.f);
        v.z = fmaxf(v.z, 0.f);
        v.w = fmaxf(v.w, 0.f);
        o4[i] = v;
    }
}

// ---------------- launcher ----------------
extern "C" void kernel_launch(void* const* d_in, const int* in_sizes, int n_in,
                              void* d_out, int out_size) {
    const float* x    = (const float*)d_in[0];
    const float* W    = (const float*)d_in[1];
    const int*   u    = (const int*)d_in[2];
    const int*   v    = (const int*)d_in[3];
    const int*   widx = (const int*)d_in[4];
    float* out = (float*)d_out;

    const int E = in_sizes[2];

    cudaMemsetAsync(d_out, 0, (size_t)out_size * sizeof(float), 0);

    fill_init_k<<<1, 256>>>();
    scatter_k<<<(E + SC_CHUNK - 1) / SC_CHUNK, 256>>>(u, v, widx, E);
    edge_mm_k<<<dim3(N_WEIGHTS, MM_GRID_Y), 256>>>(x, W, out);
    relu_k<<<784, 256>>>(out, out_size / 4);
}